// round 7
// baseline (speedup 1.0000x reference)
#include <cuda_runtime.h>
#include <cuda_bf16.h>
#include <cstdint>

// One-hot expansion: mask [1,1,256,256,48] fp32 integer labels 0..40
//   -> out [1,40,256,256,48], out[:,c] = (mask == c+1) ? 1.0f : 0.0f
//
// Streaming-store bound (503 MB writes, 12.6 MB reads).
// Layout: thread t in block b owns float4 indices (b*512 + t) and
// (b*512 + t + 256) — warp-contiguous (each warp STG.128 spans a contiguous
// 512B = 4 full 128B lines; NOT the R2 per-thread-contiguous mistake).
// Two independent stores per channel per thread double store-queue depth and
// amortize addressing. .cs hints removed (measured exactly neutral in R6).

#define N_LABELS 40

__global__ __launch_bounds__(256)
void onehot40_kernel(const float4* __restrict__ mask4,
                     float4* __restrict__ out4,
                     int vol4) {
    int i0 = blockIdx.x * 512 + threadIdx.x;   // first float4
    int i1 = i0 + 256;                         // second float4, warp-stride
    if (i1 >= vol4 + 256) return;              // full blocks only (vol4 % 512 == 0)

    float4 ma = mask4[i0];
    float4 mb = mask4[i1];

#pragma unroll
    for (int c = 0; c < N_LABELS; c++) {
        const float lab = (float)(c + 1);
        float4 ra, rb;
        ra.x = (ma.x == lab) ? 1.0f : 0.0f;
        ra.y = (ma.y == lab) ? 1.0f : 0.0f;
        ra.z = (ma.z == lab) ? 1.0f : 0.0f;
        ra.w = (ma.w == lab) ? 1.0f : 0.0f;
        rb.x = (mb.x == lab) ? 1.0f : 0.0f;
        rb.y = (mb.y == lab) ? 1.0f : 0.0f;
        rb.z = (mb.z == lab) ? 1.0f : 0.0f;
        rb.w = (mb.w == lab) ? 1.0f : 0.0f;
        size_t base = (size_t)c * (size_t)vol4;
        out4[base + (size_t)i0] = ra;
        out4[base + (size_t)i1] = rb;
    }
}

extern "C" void kernel_launch(void* const* d_in, const int* in_sizes, int n_in,
                              void* d_out, int out_size) {
    const float* mask = (const float*)d_in[0];
    float* out = (float*)d_out;

    int vol = in_sizes[0];          // 256*256*48 = 3,145,728
    int vol4 = vol / 4;             // 786,432  (divisible by 512)

    int threads = 256;
    int blocks = vol4 / 512;        // 1536 blocks, each covers 512 float4

    onehot40_kernel<<<blocks, threads>>>(
        (const float4*)mask, (float4*)out, vol4);
}